// round 5
// baseline (speedup 1.0000x reference)
#include <cuda_runtime.h>

// B=4, N=256, OBS=40, ACT=8, HEAD=8, DIM=32, T=256
// Algebra: nh/hid independent of broadcast index -> only column sums S_n,S_h (B,T);
// final gather at tgt -> ah needed at 4 rows only.
// Split-K=2 (atomic-free) for E2/NE; consumers add partials at load.
// GEMMs tiled BM=32 BN=32 BK=32, 128-thread blocks -> 512 blocks (grid-limited occ fix).

__device__ float g_E1[1024 * 256];
__device__ float g_E2[2 * 1024 * 256];
__device__ float g_NE[2 * 1024 * 256];
__device__ float g_Sn[1024];
__device__ float g_Sh[1024];
__device__ float g_AH[1024];

#define E2_HALF (1024 * 256)

// ---------------------------------------------------------------------------
__global__ void k_embed1(const float* __restrict__ x, const float* __restrict__ We1,
                         const float* __restrict__ be1) {
    __shared__ float xs[4][40];
    int r0 = blockIdx.x * 4;
    int tid = threadIdx.x;
    if (blockIdx.x == 0) {
#pragma unroll
        for (int i = 0; i < 4; i++) {
            g_Sn[i * 256 + tid] = 0.f;
            g_Sh[i * 256 + tid] = 0.f;
            g_AH[i * 256 + tid] = 0.f;
        }
    }
    if (tid < 160) {
        int rr = tid / 40, k = tid % 40;
        int row = r0 + rr;
        int b = row >> 8, i = row & 255;
        xs[rr][k] = x[b * 257 * 40 + i * 40 + k];
    }
    __syncthreads();
    float bias = be1[tid];
    float acc[4] = {bias, bias, bias, bias};
#pragma unroll
    for (int k = 0; k < 40; k++) {
        float w = We1[k * 256 + tid];
#pragma unroll
        for (int rr = 0; rr < 4; rr++) acc[rr] += xs[rr][k] * w;
    }
#pragma unroll
    for (int rr = 0; rr < 4; rr++)
        g_E1[(r0 + rr) * 256 + tid] = fmaxf(acc[rr], 0.f);
}

// ---------------------------------------------------------------------------
// Shared tiling for all GEMMs: BM=32 BN=32 BK=32, 128 threads.
// A loader: arow=tid>>2 (0..31), akq=tid&3; loads k-offsets akq*4 and 16+akq*4.
// B loader: same indices over [k][n].
// Compute:  tx=tid&7 (n quad), ty=tid>>3 (0..15, rows ty*2, ty*2+1).

#define GEMM_COMPUTE(As_, Bs_, acc_)                                           \
    _Pragma("unroll")                                                          \
    for (int kk = 0; kk < 32; kk++) {                                          \
        float2 av = *(const float2*)&As_[kk][ty * 2];                          \
        float4 bv = *(const float4*)&Bs_[kk][tx * 4];                          \
        acc_[0][0] += av.x * bv.x; acc_[0][1] += av.x * bv.y;                  \
        acc_[0][2] += av.x * bv.z; acc_[0][3] += av.x * bv.w;                  \
        acc_[1][0] += av.y * bv.x; acc_[1][1] += av.y * bv.y;                  \
        acc_[1][2] += av.y * bv.z; acc_[1][3] += av.y * bv.w;                  \
    }

#define STORE_A(dst, v0, v1)                                                   \
    {                                                                          \
        dst[akq * 4 + 0][arow] = v0.x; dst[akq * 4 + 1][arow] = v0.y;          \
        dst[akq * 4 + 2][arow] = v0.z; dst[akq * 4 + 3][arow] = v0.w;          \
        dst[16 + akq * 4 + 0][arow] = v1.x; dst[16 + akq * 4 + 1][arow] = v1.y;\
        dst[16 + akq * 4 + 2][arow] = v1.z; dst[16 + akq * 4 + 3][arow] = v1.w;\
    }

// K2: E2 partial = E1 @ We2 over K-half z. grid (8,32,2)
__global__ void __launch_bounds__(128) k_gemmE2(const float* __restrict__ E1,
                                                const float* __restrict__ We2) {
    __shared__ float As[2][32][36];
    __shared__ float Bs[2][32][32];
    int tid = threadIdx.x;
    int tx = tid & 7, ty = tid >> 3;
    int arow = tid >> 2, akq = tid & 3;
    int row0 = blockIdx.y * 32, col0 = blockIdx.x * 32, kb = blockIdx.z * 128;
    const float* aptr = E1 + (row0 + arow) * 256 + kb + akq * 4;
    const float* bptr = We2 + (kb + arow) * 256 + col0 + akq * 4;

    float4 a0 = *(const float4*)aptr;
    float4 a1 = *(const float4*)(aptr + 16);
    float4 b0 = *(const float4*)bptr;
    float4 b1 = *(const float4*)(bptr + 16);
    STORE_A(As[0], a0, a1);
    *(float4*)&Bs[0][arow][akq * 4] = b0;
    *(float4*)&Bs[0][arow][16 + akq * 4] = b1;
    __syncthreads();

    float acc[2][4] = {};
    int s = 0;
    for (int k0 = 0; k0 < 128; k0 += 32) {
        if (k0 + 32 < 128) {
            a0 = *(const float4*)(aptr + k0 + 32);
            a1 = *(const float4*)(aptr + k0 + 48);
            b0 = *(const float4*)(bptr + (size_t)(k0 + 32) * 256);
            b1 = *(const float4*)(bptr + (size_t)(k0 + 32) * 256 + 16);
        }
        GEMM_COMPUTE(As[s], Bs[s], acc)
        if (k0 + 32 < 128) {
            int ns = s ^ 1;
            STORE_A(As[ns], a0, a1);
            *(float4*)&Bs[ns][arow][akq * 4] = b0;
            *(float4*)&Bs[ns][arow][16 + akq * 4] = b1;
            __syncthreads();
            s = ns;
        }
    }
    float* outp = g_E2 + (size_t)blockIdx.z * E2_HALF;
#pragma unroll
    for (int i = 0; i < 2; i++)
        *(float4*)(outp + (row0 + ty * 2 + i) * 256 + col0 + tx * 4) =
            make_float4(acc[i][0], acc[i][1], acc[i][2], acc[i][3]);
}

// K3: NE partial = adj[:,kb:+128] @ relu(E2a+E2b+be2). z = b*2+ks. grid (8,8,8)
__global__ void __launch_bounds__(128) k_gemmNE(const float* __restrict__ adj,
                                                const float* __restrict__ be2) {
    __shared__ float As[2][32][36];
    __shared__ float Bs[2][32][32];
    int tid = threadIdx.x;
    int tx = tid & 7, ty = tid >> 3;
    int arow = tid >> 2, akq = tid & 3;
    int b = blockIdx.z >> 1, ks = blockIdx.z & 1, kb = ks * 128;
    int row0 = blockIdx.y * 32, col0 = blockIdx.x * 32;
    const float* aptr = adj + (row0 + arow) * 256 + kb + akq * 4;
    const float* pa = g_E2 + (size_t)(b * 256 + kb + arow) * 256 + col0 + akq * 4;
    const float* pb = pa + E2_HALF;
    float4 bi0 = *(const float4*)(be2 + col0 + akq * 4);
    float4 bi1 = *(const float4*)(be2 + col0 + 16 + akq * 4);

    float4 a0 = *(const float4*)aptr;
    float4 a1 = *(const float4*)(aptr + 16);
    float4 e0 = *(const float4*)pa, f0 = *(const float4*)pb;
    float4 e1 = *(const float4*)(pa + 16), f1 = *(const float4*)(pb + 16);
    STORE_A(As[0], a0, a1);
    *(float4*)&Bs[0][arow][akq * 4] =
        make_float4(fmaxf(e0.x + f0.x + bi0.x, 0.f), fmaxf(e0.y + f0.y + bi0.y, 0.f),
                    fmaxf(e0.z + f0.z + bi0.z, 0.f), fmaxf(e0.w + f0.w + bi0.w, 0.f));
    *(float4*)&Bs[0][arow][16 + akq * 4] =
        make_float4(fmaxf(e1.x + f1.x + bi1.x, 0.f), fmaxf(e1.y + f1.y + bi1.y, 0.f),
                    fmaxf(e1.z + f1.z + bi1.z, 0.f), fmaxf(e1.w + f1.w + bi1.w, 0.f));
    __syncthreads();

    float acc[2][4] = {};
    int s = 0;
    for (int k0 = 0; k0 < 128; k0 += 32) {
        if (k0 + 32 < 128) {
            a0 = *(const float4*)(aptr + k0 + 32);
            a1 = *(const float4*)(aptr + k0 + 48);
            e0 = *(const float4*)(pa + (size_t)(k0 + 32) * 256);
            f0 = *(const float4*)(pb + (size_t)(k0 + 32) * 256);
            e1 = *(const float4*)(pa + (size_t)(k0 + 32) * 256 + 16);
            f1 = *(const float4*)(pb + (size_t)(k0 + 32) * 256 + 16);
        }
        GEMM_COMPUTE(As[s], Bs[s], acc)
        if (k0 + 32 < 128) {
            int ns = s ^ 1;
            STORE_A(As[ns], a0, a1);
            *(float4*)&Bs[ns][arow][akq * 4] =
                make_float4(fmaxf(e0.x + f0.x + bi0.x, 0.f), fmaxf(e0.y + f0.y + bi0.y, 0.f),
                            fmaxf(e0.z + f0.z + bi0.z, 0.f), fmaxf(e0.w + f0.w + bi0.w, 0.f));
            *(float4*)&Bs[ns][arow][16 + akq * 4] =
                make_float4(fmaxf(e1.x + f1.x + bi1.x, 0.f), fmaxf(e1.y + f1.y + bi1.y, 0.f),
                            fmaxf(e1.z + f1.z + bi1.z, 0.f), fmaxf(e1.w + f1.w + bi1.w, 0.f));
            __syncthreads();
            s = ns;
        }
    }
    float* outp = g_NE + (size_t)ks * E2_HALF + (size_t)(b * 256) * 256;
#pragma unroll
    for (int i = 0; i < 2; i++)
        *(float4*)(outp + (row0 + ty * 2 + i) * 256 + col0 + tx * 4) =
            make_float4(acc[i][0], acc[i][1], acc[i][2], acc[i][3]);
}

// K4: column sums of relu((NEa+NEb)@W + bias); z: 0->Wn/Sn, 1->Wh/Sh. grid (8,32,2)
__global__ void __launch_bounds__(128) k_colsum(const float* __restrict__ Wn,
                                                const float* __restrict__ bn,
                                                const float* __restrict__ Wh,
                                                const float* __restrict__ bh) {
    __shared__ float As[2][32][36];
    __shared__ float Bs[2][32][32];
    __shared__ float red[32];
    const float* W = blockIdx.z ? Wh : Wn;
    const float* bias = blockIdx.z ? bh : bn;
    float* S = blockIdx.z ? g_Sh : g_Sn;
    int tid = threadIdx.x;
    int tx = tid & 7, ty = tid >> 3;
    int arow = tid >> 2, akq = tid & 3;
    int row0 = blockIdx.y * 32, col0 = blockIdx.x * 32;
    int batch = blockIdx.y >> 3;
    const float* pa = g_NE + (size_t)(row0 + arow) * 256 + akq * 4;
    const float* pb = pa + E2_HALF;
    const float* bptr = W + arow * 256 + col0 + akq * 4;

    float4 u0 = *(const float4*)pa, v0 = *(const float4*)pb;
    float4 u1 = *(const float4*)(pa + 16), v1 = *(const float4*)(pb + 16);
    float4 b0 = *(const float4*)bptr;
    float4 b1 = *(const float4*)(bptr + 16);
    float4 s0 = make_float4(u0.x + v0.x, u0.y + v0.y, u0.z + v0.z, u0.w + v0.w);
    float4 s1 = make_float4(u1.x + v1.x, u1.y + v1.y, u1.z + v1.z, u1.w + v1.w);
    STORE_A(As[0], s0, s1);
    *(float4*)&Bs[0][arow][akq * 4] = b0;
    *(float4*)&Bs[0][arow][16 + akq * 4] = b1;
    __syncthreads();

    float acc[2][4] = {};
    int s = 0;
    for (int k0 = 0; k0 < 256; k0 += 32) {
        if (k0 + 32 < 256) {
            u0 = *(const float4*)(pa + k0 + 32);
            v0 = *(const float4*)(pb + k0 + 32);
            u1 = *(const float4*)(pa + k0 + 48);
            v1 = *(const float4*)(pb + k0 + 48);
            b0 = *(const float4*)(bptr + (size_t)(k0 + 32) * 256);
            b1 = *(const float4*)(bptr + (size_t)(k0 + 32) * 256 + 16);
        }
        GEMM_COMPUTE(As[s], Bs[s], acc)
        if (k0 + 32 < 256) {
            int ns = s ^ 1;
            s0 = make_float4(u0.x + v0.x, u0.y + v0.y, u0.z + v0.z, u0.w + v0.w);
            s1 = make_float4(u1.x + v1.x, u1.y + v1.y, u1.z + v1.z, u1.w + v1.w);
            STORE_A(As[ns], s0, s1);
            *(float4*)&Bs[ns][arow][akq * 4] = b0;
            *(float4*)&Bs[ns][arow][16 + akq * 4] = b1;
            __syncthreads();
            s = ns;
        }
    }
    if (tid < 32) red[tid] = 0.f;
    __syncthreads();
    float4 bi = *(const float4*)(bias + col0 + tx * 4);
    float ba4[4] = {bi.x, bi.y, bi.z, bi.w};
#pragma unroll
    for (int j = 0; j < 4; j++) {
        float sv = fmaxf(acc[0][j] + ba4[j], 0.f) + fmaxf(acc[1][j] + ba4[j], 0.f);
        sv += __shfl_xor_sync(0xffffffffu, sv, 8);
        sv += __shfl_xor_sync(0xffffffffu, sv, 16);
        if ((tid & 31) < 8) atomicAdd(&red[tx * 4 + j], sv);
    }
    __syncthreads();
    if (tid < 32) atomicAdd(&S[batch * 256 + col0 + tid], red[tid]);
}

// ---------------------------------------------------------------------------
__global__ void k_ah(const float* __restrict__ x, const float* __restrict__ Wl,
                     const float* __restrict__ be2) {
    __shared__ float vs[64];
    int b = blockIdx.x >> 2, kseg = blockIdx.x & 3;
    int t = threadIdx.x;
    int tgt = (int)x[b * 257 * 40 + 256 * 40];
    if (t < 64) {
        int col = kseg * 64 + t;
        size_t idx = (size_t)(b * 256 + tgt) * 256 + col;
        vs[t] = fmaxf(g_E2[idx] + g_E2[E2_HALF + idx] + be2[col], 0.f);
    }
    __syncthreads();
    float acc = 0.f;
#pragma unroll 8
    for (int k = 0; k < 64; k++)
        acc += vs[k] * Wl[(kseg * 64 + k) * 256 + t];
    atomicAdd(&g_AH[b * 256 + t], acc);
}

// ---------------------------------------------------------------------------
__global__ void k_final(const float* __restrict__ bl, const float* __restrict__ Wa,
                        const float* __restrict__ ba, float* __restrict__ out) {
    __shared__ float od[32];
    int b = blockIdx.x, tid = threadIdx.x;
    int h = tid >> 5, d = tid & 31;
    int t = d * 8 + h;
    float ahv = fmaxf(g_AH[b * 256 + t] + bl[t], 0.f);
    float logit = ahv * g_Sn[b * 256 + t];
    float m = logit;
#pragma unroll
    for (int o = 16; o > 0; o >>= 1) m = fmaxf(m, __shfl_xor_sync(0xffffffffu, m, o));
    float e = expf(logit - m);
    float ssum = e;
#pragma unroll
    for (int o = 16; o > 0; o >>= 1) ssum += __shfl_xor_sync(0xffffffffu, ssum, o);
    float val = (e / ssum) * g_Sh[b * 256 + t] * 0.125f;
    if (tid < 32) od[tid] = 0.f;
    __syncthreads();
    atomicAdd(&od[d], val);
    __syncthreads();
    if (tid < 8) {
        float acc = ba[tid];
#pragma unroll
        for (int dd = 0; dd < 32; dd++) acc += od[dd] * Wa[dd * 8 + tid];
        out[b * 8 + tid] = acc;
    }
    (void)h;
}

// ---------------------------------------------------------------------------
extern "C" void kernel_launch(void* const* d_in, const int* in_sizes, int n_in,
                              void* d_out, int out_size) {
    const float* x   = (const float*)d_in[0];
    const float* adj = (const float*)d_in[1];
    const float* We1 = (const float*)d_in[2];
    const float* be1 = (const float*)d_in[3];
    const float* We2 = (const float*)d_in[4];
    const float* be2 = (const float*)d_in[5];
    const float* Wl  = (const float*)d_in[6];
    const float* bl  = (const float*)d_in[7];
    const float* Wn  = (const float*)d_in[8];
    const float* bn  = (const float*)d_in[9];
    const float* Wh  = (const float*)d_in[10];
    const float* bh  = (const float*)d_in[11];
    const float* Wa  = (const float*)d_in[12];
    const float* ba  = (const float*)d_in[13];
    float* out = (float*)d_out;

    float* pE1;
    cudaGetSymbolAddress((void**)&pE1, g_E1);

    k_embed1<<<256, 256>>>(x, We1, be1);
    k_gemmE2<<<dim3(8, 32, 2), 128>>>(pE1, We2);
    k_gemmNE<<<dim3(8, 8, 8), 128>>>(adj, be2);
    k_colsum<<<dim3(8, 32, 2), 128>>>(Wn, bn, Wh, bh);
    k_ah<<<16, 256>>>(x, Wl, be2);
    k_final<<<4, 256>>>(bl, Wa, ba, out);

    (void)in_sizes; (void)n_in; (void)out_size;
}

// round 6
// speedup vs baseline: 1.0553x; 1.0553x over previous
#include <cuda_runtime.h>
#include <cstdint>

// B=4, N=256, OBS=40, ACT=8, HEAD=8, DIM=32, T=256
// Algebra: nh/hid independent of broadcast index -> only column sums S_n,S_h;
// final gather at tgt -> ah needed at 4 rows only.
// GEMMs: BM=64 BN=32 BK=32, 256 thr, 2x4 microtile, cp.async 3-stage pipeline.
// Split-K=2 for E2/NE with tiny fuse kernels producing relu'd/summed operands.

__device__ float g_E1[1024 * 256];
__device__ float g_E2[2 * 1024 * 256];   // ksplit partials of E1@We2
__device__ float g_E2f[1024 * 256];      // relu(E2a+E2b+be2)
__device__ float g_NE[2 * 1024 * 256];   // ksplit partials of adj@E2f
__device__ float g_NEf[1024 * 256];      // NEa+NEb
__device__ float g_Sn[1024];
__device__ float g_Sh[1024];
__device__ float g_AH[1024];

#define E2_HALF (1024 * 256)
#define AS_PAD 36
#define AS_BYTES (64 * AS_PAD * 4)
#define BS_BYTES (32 * 32 * 4)

__device__ __forceinline__ void cp16(uint32_t dst, const void* src) {
    asm volatile("cp.async.ca.shared.global [%0], [%1], 16;\n" :: "r"(dst), "l"(src));
}
#define CP_COMMIT() asm volatile("cp.async.commit_group;\n" ::)
#define CP_WAIT1()  asm volatile("cp.async.wait_group 1;\n" ::)

// ---------------------------------------------------------------------------
__global__ void k_embed1(const float* __restrict__ x, const float* __restrict__ We1,
                         const float* __restrict__ be1) {
    __shared__ float xs[4][40];
    int r0 = blockIdx.x * 4;
    int tid = threadIdx.x;
    if (blockIdx.x == 0) {
#pragma unroll
        for (int i = 0; i < 4; i++) {
            g_Sn[i * 256 + tid] = 0.f;
            g_Sh[i * 256 + tid] = 0.f;
            g_AH[i * 256 + tid] = 0.f;
        }
    }
    if (tid < 160) {
        int rr = tid / 40, k = tid % 40;
        int row = r0 + rr;
        int b = row >> 8, i = row & 255;
        xs[rr][k] = x[b * 257 * 40 + i * 40 + k];
    }
    __syncthreads();
    float bias = be1[tid];
    float acc[4] = {bias, bias, bias, bias};
#pragma unroll
    for (int k = 0; k < 40; k++) {
        float w = We1[k * 256 + tid];
#pragma unroll
        for (int rr = 0; rr < 4; rr++) acc[rr] += xs[rr][k] * w;
    }
#pragma unroll
    for (int rr = 0; rr < 4; rr++)
        g_E1[(r0 + rr) * 256 + tid] = fmaxf(acc[rr], 0.f);
}

// ---------------------------------------------------------------------------
// GEMM core: BM=64 BN=32 BK=32, 256 threads, 2x4 microtile, 3-stage cp.async.
// As[s][m][AS_PAD] (row-major tile), Bs[s][k][n].
// Loaders: A: arow=tid>>2 (0..63), akq=tid&3 -> two 16B at k=akq*4, akq*4+16.
//          B: brow=tid>>3 (0..31), bcq=tid&7 -> one 16B at n=bcq*4.
// Compute: tx=tid&7 (cols tx*4), ty=tid>>3 (rows ty*2, ty*2+1).

#define GEMM_PIPE_BODY(T, AGLOBAL_ROWSTRIDE)                                    \
    uint32_t sA = (uint32_t)__cvta_generic_to_shared(&As[0][0][0]);             \
    uint32_t sB = (uint32_t)__cvta_generic_to_shared(&Bs[0][0][0]);             \
    uint32_t dA0 = sA + (uint32_t)(arow * AS_PAD + akq * 4) * 4;                \
    uint32_t dA1 = dA0 + 64;                                                    \
    uint32_t dB  = sB + (uint32_t)(brow * 32 + bcq * 4) * 4;                    \
    /* prologue: tiles 0,1 */                                                   \
    cp16(dA0, aBase); cp16(dA1, aBase + 16); cp16(dB, bBase);                   \
    CP_COMMIT();                                                                \
    cp16(dA0 + AS_BYTES, aBase + 32); cp16(dA1 + AS_BYTES, aBase + 48);         \
    cp16(dB + BS_BYTES, bBase + (size_t)32 * AGLOBAL_ROWSTRIDE);                \
    CP_COMMIT();                                                                \
    float acc[2][4] = {};                                                       \
    for (int t = 0; t < T; t++) {                                               \
        int s = t - (t >= 3 ? 3 : 0); s = (t % 3);                              \
        CP_WAIT1();                                                             \
        __syncthreads();                                                        \
        _Pragma("unroll")                                                       \
        for (int kk = 0; kk < 32; kk++) {                                       \
            float a0 = As[s][ty * 2 + 0][kk];                                   \
            float a1 = As[s][ty * 2 + 1][kk];                                   \
            float4 bv = *(const float4*)&Bs[s][kk][tx * 4];                     \
            acc[0][0] += a0 * bv.x; acc[0][1] += a0 * bv.y;                     \
            acc[0][2] += a0 * bv.z; acc[0][3] += a0 * bv.w;                     \
            acc[1][0] += a1 * bv.x; acc[1][1] += a1 * bv.y;                     \
            acc[1][2] += a1 * bv.z; acc[1][3] += a1 * bv.w;                     \
        }                                                                       \
        if (t + 2 < T) {                                                        \
            int ns = (t + 2) % 3;                                               \
            const float* ag = aBase + (t + 2) * 32;                             \
            cp16(dA0 + ns * AS_BYTES, ag);                                      \
            cp16(dA1 + ns * AS_BYTES, ag + 16);                                 \
            cp16(dB + ns * BS_BYTES,                                            \
                 bBase + (size_t)((t + 2) * 32) * AGLOBAL_ROWSTRIDE);           \
        }                                                                       \
        CP_COMMIT();                                                            \
    }

// K2: E2 partial = E1 @ We2 over K-half z. grid (8,16,2), 256 thr.
__global__ void __launch_bounds__(256) k_gemmE2(const float* __restrict__ E1,
                                                const float* __restrict__ We2) {
    __shared__ float As[3][64][AS_PAD];
    __shared__ float Bs[3][32][32];
    int tid = threadIdx.x;
    int tx = tid & 7, ty = tid >> 3;
    int arow = tid >> 2, akq = tid & 3;
    int brow = tid >> 3, bcq = tid & 7;
    int row0 = blockIdx.y * 64, col0 = blockIdx.x * 32, kb = blockIdx.z * 128;
    const float* aBase = E1 + (row0 + arow) * 256 + kb + akq * 4;
    const float* bBase = We2 + (size_t)(kb + brow) * 256 + col0 + bcq * 4;
    GEMM_PIPE_BODY(4, 256)
    float* outp = g_E2 + (size_t)blockIdx.z * E2_HALF;
#pragma unroll
    for (int i = 0; i < 2; i++)
        *(float4*)(outp + (size_t)(row0 + ty * 2 + i) * 256 + col0 + tx * 4) =
            make_float4(acc[i][0], acc[i][1], acc[i][2], acc[i][3]);
}

// fuse: E2f = relu(E2a + E2b + be2). grid 256, block 256 (float4 per thread).
__global__ void k_fuseE2(const float* __restrict__ be2) {
    int i = blockIdx.x * 256 + threadIdx.x;   // float4 index, 65536 total
    float4 a = ((const float4*)g_E2)[i];
    float4 b = ((const float4*)(g_E2 + E2_HALF))[i];
    float4 c = ((const float4*)be2)[i & 63];
    ((float4*)g_E2f)[i] = make_float4(
        fmaxf(a.x + b.x + c.x, 0.f), fmaxf(a.y + b.y + c.y, 0.f),
        fmaxf(a.z + b.z + c.z, 0.f), fmaxf(a.w + b.w + c.w, 0.f));
}

// K3: NE partial = adj[:,kb:+128] @ E2f[b][kb:+128]. z=b*2+ks. grid (8,4,8).
__global__ void __launch_bounds__(256) k_gemmNE(const float* __restrict__ adj) {
    __shared__ float As[3][64][AS_PAD];
    __shared__ float Bs[3][32][32];
    int tid = threadIdx.x;
    int tx = tid & 7, ty = tid >> 3;
    int arow = tid >> 2, akq = tid & 3;
    int brow = tid >> 3, bcq = tid & 7;
    int b = blockIdx.z >> 1, ks = blockIdx.z & 1, kb = ks * 128;
    int row0 = blockIdx.y * 64, col0 = blockIdx.x * 32;
    const float* aBase = adj + (row0 + arow) * 256 + kb + akq * 4;
    const float* bBase = g_E2f + (size_t)(b * 256 + kb + brow) * 256 + col0 + bcq * 4;
    GEMM_PIPE_BODY(4, 256)
    float* outp = g_NE + (size_t)ks * E2_HALF + (size_t)(b * 256) * 256;
#pragma unroll
    for (int i = 0; i < 2; i++)
        *(float4*)(outp + (size_t)(row0 + ty * 2 + i) * 256 + col0 + tx * 4) =
            make_float4(acc[i][0], acc[i][1], acc[i][2], acc[i][3]);
}

// fuse: NEf = NEa + NEb. grid 256, block 256.
__global__ void k_fuseNE() {
    int i = blockIdx.x * 256 + threadIdx.x;
    float4 a = ((const float4*)g_NE)[i];
    float4 b = ((const float4*)(g_NE + E2_HALF))[i];
    ((float4*)g_NEf)[i] = make_float4(a.x + b.x, a.y + b.y, a.z + b.z, a.w + b.w);
}

// K4: column sums of relu(NEf@W + bias); z: 0->Wn/Sn, 1->Wh/Sh. grid (8,16,2).
__global__ void __launch_bounds__(256) k_colsum(const float* __restrict__ Wn,
                                                const float* __restrict__ bn,
                                                const float* __restrict__ Wh,
                                                const float* __restrict__ bh) {
    __shared__ float As[3][64][AS_PAD];
    __shared__ float Bs[3][32][32];
    __shared__ float red[32];
    const float* W = blockIdx.z ? Wh : Wn;
    const float* bias = blockIdx.z ? bh : bn;
    float* S = blockIdx.z ? g_Sh : g_Sn;
    int tid = threadIdx.x;
    int tx = tid & 7, ty = tid >> 3;
    int arow = tid >> 2, akq = tid & 3;
    int brow = tid >> 3, bcq = tid & 7;
    int row0 = blockIdx.y * 64, col0 = blockIdx.x * 32;
    int batch = blockIdx.y >> 2;
    const float* aBase = g_NEf + (size_t)(row0 + arow) * 256 + akq * 4;
    const float* bBase = W + (size_t)brow * 256 + col0 + bcq * 4;
    GEMM_PIPE_BODY(8, 256)
    if (tid < 32) red[tid] = 0.f;
    __syncthreads();
    float4 bi = *(const float4*)(bias + col0 + tx * 4);
    float ba4[4] = {bi.x, bi.y, bi.z, bi.w};
#pragma unroll
    for (int j = 0; j < 4; j++) {
        float sv = fmaxf(acc[0][j] + ba4[j], 0.f) + fmaxf(acc[1][j] + ba4[j], 0.f);
        sv += __shfl_xor_sync(0xffffffffu, sv, 8);
        sv += __shfl_xor_sync(0xffffffffu, sv, 16);
        if ((tid & 31) < 8) atomicAdd(&red[tx * 4 + j], sv);
    }
    __syncthreads();
    if (tid < 32) atomicAdd(&S[batch * 256 + col0 + tid], red[tid]);
}

// ---------------------------------------------------------------------------
// ah split-K partials from E2f: grid 16 (4 batches x 4 k-segments of 64).
__global__ void k_ah(const float* __restrict__ x, const float* __restrict__ Wl) {
    __shared__ float vs[64];
    int b = blockIdx.x >> 2, kseg = blockIdx.x & 3;
    int t = threadIdx.x;
    int tgt = (int)x[b * 257 * 40 + 256 * 40];
    if (t < 64)
        vs[t] = g_E2f[(size_t)(b * 256 + tgt) * 256 + kseg * 64 + t];
    __syncthreads();
    float acc = 0.f;
#pragma unroll 8
    for (int k = 0; k < 64; k++)
        acc += vs[k] * Wl[(kseg * 64 + k) * 256 + t];
    atomicAdd(&g_AH[b * 256 + t], acc);
}

// ---------------------------------------------------------------------------
__global__ void k_final(const float* __restrict__ bl, const float* __restrict__ Wa,
                        const float* __restrict__ ba, float* __restrict__ out) {
    __shared__ float od[32];
    int b = blockIdx.x, tid = threadIdx.x;
    int h = tid >> 5, d = tid & 31;
    int t = d * 8 + h;
    float ahv = fmaxf(g_AH[b * 256 + t] + bl[t], 0.f);
    float logit = ahv * g_Sn[b * 256 + t];
    float m = logit;
#pragma unroll
    for (int o = 16; o > 0; o >>= 1) m = fmaxf(m, __shfl_xor_sync(0xffffffffu, m, o));
    float e = expf(logit - m);
    float ssum = e;
#pragma unroll
    for (int o = 16; o > 0; o >>= 1) ssum += __shfl_xor_sync(0xffffffffu, ssum, o);
    float val = (e / ssum) * g_Sh[b * 256 + t] * 0.125f;
    if (tid < 32) od[tid] = 0.f;
    __syncthreads();
    atomicAdd(&od[d], val);
    __syncthreads();
    if (tid < 8) {
        float acc = ba[tid];
#pragma unroll
        for (int dd = 0; dd < 32; dd++) acc += od[dd] * Wa[dd * 8 + tid];
        out[b * 8 + tid] = acc;
    }
    (void)h;
}

// ---------------------------------------------------------------------------
extern "C" void kernel_launch(void* const* d_in, const int* in_sizes, int n_in,
                              void* d_out, int out_size) {
    const float* x   = (const float*)d_in[0];
    const float* adj = (const float*)d_in[1];
    const float* We1 = (const float*)d_in[2];
    const float* be1 = (const float*)d_in[3];
    const float* We2 = (const float*)d_in[4];
    const float* be2 = (const float*)d_in[5];
    const float* Wl  = (const float*)d_in[6];
    const float* bl  = (const float*)d_in[7];
    const float* Wn  = (const float*)d_in[8];
    const float* bn  = (const float*)d_in[9];
    const float* Wh  = (const float*)d_in[10];
    const float* bh  = (const float*)d_in[11];
    const float* Wa  = (const float*)d_in[12];
    const float* ba  = (const float*)d_in[13];
    float* out = (float*)d_out;

    float* pE1;
    cudaGetSymbolAddress((void**)&pE1, g_E1);

    k_embed1<<<256, 256>>>(x, We1, be1);
    k_gemmE2<<<dim3(8, 16, 2), 256>>>(pE1, We2);
    k_fuseE2<<<256, 256>>>(be2);
    k_gemmNE<<<dim3(8, 4, 8), 256>>>(adj);
    k_fuseNE<<<256, 256>>>();
    k_colsum<<<dim3(8, 16, 2), 256>>>(Wn, bn, Wh, bh);
    k_ah<<<16, 256>>>(x, Wl);
    k_final<<<4, 256>>>(bl, Wa, ba, out);

    (void)in_sizes; (void)n_in; (void)out_size;
}